// round 11
// baseline (speedup 1.0000x reference)
#include <cuda_runtime.h>

// Router: logits = x @ wg^T + gr @ gm^T ; std-normalized softmax; top-2;
// mask expert E-1; renormalize.
// Output layout (float32): [gates 2T | indices 2T | logits 8T]
//
// R11: minimum-L1 design. Evidence from R7-R10: L1 wavefront work is the
// binding resource; smem staging pays it twice (LDGSTS write + LDS read).
// Here: NO smem. x goes global->register via octet-dedup'd LDG.128
// (4 octets read identical addrs -> 1 wavefront/token-row, R9-proven);
// wg is L1-resident via __ldg (x uses __ldcs evict-first to protect it).
// NT=8 octet split keeps wg amortized over 8 tokens, acc = 32 regs.
// L1 work ~64 wf per 4KB of x (~7us) << 17us DRAM floor.

constexpr int D       = 2048;
constexpr int E       = 8;
constexpr int NT      = 8;            // tokens per warp
constexpr int THREADS = 448;          // 14 warps, 1 CTA/SM
constexpr int WARPS   = THREADS / 32;
constexpr int CHUNKS  = D / 4;        // 16B chunks per row = 512
constexpr int ITERS   = CHUNKS / 32;  // 16 iterations (32 chunks each)
constexpr int GRID    = 148;

__device__ __forceinline__ unsigned long long ffma2(unsigned long long a,
                                                    unsigned long long b,
                                                    unsigned long long c) {
    unsigned long long d;
    asm("fma.rn.f32x2 %0, %1, %2, %3;" : "=l"(d) : "l"(a), "l"(b), "l"(c));
    return d;
}

__device__ __forceinline__ float pairsum(unsigned long long v) {
    float2 f;
    f.x = __uint_as_float((unsigned int)(v & 0xffffffffull));
    f.y = __uint_as_float((unsigned int)(v >> 32));
    return f.x + f.y;
}

// 16B streaming load (evict-first), returned as two packed f32 pairs
__device__ __forceinline__ ulonglong2 ldcs16(const ulonglong2* p) {
    ulonglong2 v;
    asm volatile("ld.global.cs.v2.u64 {%0, %1}, [%2];"
                 : "=l"(v.x), "=l"(v.y) : "l"(p));
    return v;
}

// 16B cached load (keep in L1) for wg
__device__ __forceinline__ ulonglong2 ldg16(const ulonglong2* p) {
    ulonglong2 v;
    asm volatile("ld.global.ca.v2.u64 {%0, %1}, [%2];"
                 : "=l"(v.x), "=l"(v.y) : "l"(p));
    return v;
}

__global__ void __launch_bounds__(THREADS, 1)
router_kernel(const float* __restrict__ x,
              const float* __restrict__ wg,
              const float* __restrict__ gm,
              const float* __restrict__ gr,
              float* __restrict__ out_gates,
              float* __restrict__ out_idx,
              float* __restrict__ out_logits,
              int nGroups) {
    const int lane = threadIdx.x & 31;
    const int wid  = threadIdx.x >> 5;
    const int l8   = lane & 7;        // position within octet
    const int e0   = (lane >> 3) * 2; // this octet's first expert

    const ulonglong2* w2 = reinterpret_cast<const ulonglong2*>(wg);

    // one unit per warp; 148x14 = 2072 warps cover 2048 units
    const int g = blockIdx.x + gridDim.x * wid;

    if (g < nGroups) {
        const int t0 = g * NT;
        const ulonglong2* xr =
            reinterpret_cast<const ulonglong2*>(x + (size_t)t0 * D);
        // token j's chunk c is xr[j*CHUNKS + c]

        unsigned long long acc[NT][2];
        #pragma unroll
        for (int j = 0; j < NT; j++) { acc[j][0] = 0ull; acc[j][1] = 0ull; }

        #pragma unroll 2
        for (int it = 0; it < ITERS; it++) {
            #pragma unroll
            for (int half = 0; half < 2; half++) {
                const int cA = it * 32 + half * 16 + l8;   // k-step A
                const int cB = cA + 8;                     // k-step B

                // batch 16 x loads (8 tokens x 2 k-steps) for MLP;
                // octets read identical addresses -> 1 wavefront each
                ulonglong2 xA[NT], xB[NT];
                #pragma unroll
                for (int j = 0; j < NT; j++) {
                    xA[j] = ldcs16(xr + j * CHUNKS + cA);
                    xB[j] = ldcs16(xr + j * CHUNKS + cB);
                }
                // wg from L1 (4 distinct experts x 128B region = 4 wf)
                ulonglong2 wA0 = ldg16(w2 + e0 * CHUNKS + cA);
                ulonglong2 wA1 = ldg16(w2 + (e0 + 1) * CHUNKS + cA);
                ulonglong2 wB0 = ldg16(w2 + e0 * CHUNKS + cB);
                ulonglong2 wB1 = ldg16(w2 + (e0 + 1) * CHUNKS + cB);

                #pragma unroll
                for (int j = 0; j < NT; j++) {
                    acc[j][0] = ffma2(xA[j].x, wA0.x, acc[j][0]);
                    acc[j][0] = ffma2(xA[j].y, wA0.y, acc[j][0]);
                    acc[j][1] = ffma2(xA[j].x, wA1.x, acc[j][1]);
                    acc[j][1] = ffma2(xA[j].y, wA1.y, acc[j][1]);
                    acc[j][0] = ffma2(xB[j].x, wB0.x, acc[j][0]);
                    acc[j][0] = ffma2(xB[j].y, wB0.y, acc[j][0]);
                    acc[j][1] = ffma2(xB[j].x, wB1.x, acc[j][1]);
                    acc[j][1] = ffma2(xB[j].y, wB1.y, acc[j][1]);
                }
            }
        }

        // ---- reduce within each octet (3-step butterfly) ----
        float red[NT][2];
        #pragma unroll
        for (int j = 0; j < NT; j++) {
            #pragma unroll
            for (int e = 0; e < 2; e++) {
                float s = pairsum(acc[j][e]);
                s += __shfl_xor_sync(0xffffffffu, s, 4);
                s += __shfl_xor_sync(0xffffffffu, s, 2);
                s += __shfl_xor_sync(0xffffffffu, s, 1);
                red[j][e] = s;
            }
        }

        // lane (octet q, l8=j) keeps token t0+j's logits for experts
        // 2q, 2q+1; gather all 8 experts onto lanes 0-7.
        float s0 = red[0][0], s1 = red[0][1];
        #pragma unroll
        for (int jj = 1; jj < NT; jj++)
            if (l8 == jj) { s0 = red[jj][0]; s1 = red[jj][1]; }

        float logit[E];
        logit[0] = s0;
        logit[1] = s1;
        logit[2] = __shfl_sync(0xffffffffu, s0, l8 + 8);
        logit[3] = __shfl_sync(0xffffffffu, s1, l8 + 8);
        logit[4] = __shfl_sync(0xffffffffu, s0, l8 + 16);
        logit[5] = __shfl_sync(0xffffffffu, s1, l8 + 16);
        logit[6] = __shfl_sync(0xffffffffu, s0, l8 + 24);
        logit[7] = __shfl_sync(0xffffffffu, s1, l8 + 24);

        if (lane < NT) {
            const int t = t0 + lane;

            float4 g0 = __ldg(reinterpret_cast<const float4*>(gr + (size_t)t * E));
            float4 g1 = __ldg(reinterpret_cast<const float4*>(gr + (size_t)t * E + 4));
            float grv[8] = {g0.x, g0.y, g0.z, g0.w, g1.x, g1.y, g1.z, g1.w};
            float lg[E];
            #pragma unroll
            for (int f = 0; f < E; f++) {
                float s = logit[f];
                #pragma unroll
                for (int e = 0; e < E; e++)
                    s = fmaf(grv[e], __ldg(gm + f * E + e), s);
                lg[f] = s;
            }

            // unbiased std (ddof=1) over E=8
            float mean = 0.f;
            #pragma unroll
            for (int f = 0; f < E; f++) mean += lg[f];
            mean *= (1.f / E);
            float var = 0.f;
            #pragma unroll
            for (int f = 0; f < E; f++) {
                float d = lg[f] - mean;
                var = fmaf(d, d, var);
            }
            float inv_std = rsqrtf(var * (1.f / (E - 1)));

            float z[E], m = -3.402823466e+38f;
            #pragma unroll
            for (int f = 0; f < E; f++) {
                z[f] = lg[f] * inv_std;
                m = fmaxf(m, z[f]);
            }
            float p[E], psum = 0.f;
            #pragma unroll
            for (int f = 0; f < E; f++) {
                p[f] = __expf(z[f] - m);
                psum += p[f];
            }
            float inv_psum = 1.f / psum;
            #pragma unroll
            for (int f = 0; f < E; f++) p[f] *= inv_psum;

            // stable top-2 (descending, lower index wins ties)
            int i1 = 0; float v1 = p[0];
            #pragma unroll
            for (int f = 1; f < E; f++)
                if (p[f] > v1) { v1 = p[f]; i1 = f; }
            int i2; float v2;
            if (i1 == 0) { i2 = 1; v2 = p[1]; } else { i2 = 0; v2 = p[0]; }
            #pragma unroll
            for (int f = 1; f < E; f++)
                if (f != i1 && p[f] > v2) { v2 = p[f]; i2 = f; }

            float gg1 = (i1 == E - 1) ? 0.f : v1;
            float gg2 = (i2 == E - 1) ? 0.f : v2;
            float inv_s = 1.f / (gg1 + gg2);
            gg1 *= inv_s; gg2 *= inv_s;

            float2 gpair; gpair.x = gg1; gpair.y = gg2;
            *reinterpret_cast<float2*>(out_gates + (size_t)2 * t) = gpair;
            float2 ipair; ipair.x = (float)i1; ipair.y = (float)i2;
            *reinterpret_cast<float2*>(out_idx + (size_t)2 * t) = ipair;

            float4 L0; L0.x = lg[0]; L0.y = lg[1]; L0.z = lg[2]; L0.w = lg[3];
            float4 L1; L1.x = lg[4]; L1.y = lg[5]; L1.z = lg[6]; L1.w = lg[7];
            float4* olr = reinterpret_cast<float4*>(out_logits + (size_t)t * E);
            olr[0] = L0;
            olr[1] = L1;
        }
    }
}

extern "C" void kernel_launch(void* const* d_in, const int* in_sizes, int n_in,
                              void* d_out, int out_size) {
    const float* x  = (const float*)d_in[0];   // [T, D]
    const float* wg = (const float*)d_in[1];   // [E, D]
    const float* gm = (const float*)d_in[2];   // [E, E]
    const float* gr = (const float*)d_in[3];   // [T, E]

    const int T = in_sizes[0] / D;
    float* out       = (float*)d_out;
    float* out_gates = out;                       // [T,2]
    float* out_idx   = out + (size_t)2 * T;       // [T,2] as float
    float* out_logit = out + (size_t)4 * T;       // [T,8]

    const int nGroups = T / NT;                   // 2048
    router_kernel<<<GRID, THREADS>>>(x, wg, gm, gr,
                                     out_gates, out_idx, out_logit,
                                     nGroups);
}